// round 15
// baseline (speedup 1.0000x reference)
#include <cuda_runtime.h>
#include <cuda_bf16.h>
#include <math.h>

#define NNODE 94
#define MAXB  16384
#define NOUT  6400
#define KP    96
#define NS    (KP / 16)    // 6

typedef unsigned long long u64;
typedef unsigned int u32;
typedef unsigned short u16;

#define A_RECS  (8 * NS * 2 * 32)    // 3072 (fc A tile, 128 rows)
#define B_RECS  (16 * NS * 32)       // 3072 (128-col B tile)
#define AG_RECS (6 * NS * 2 * 32)    // 2304 (adjacency tile, 96 rows)
#define NMT     (MAXB / 128)         // 128
#define NNT     (NOUT / 128)         // 50
#define NTPC    10                   // fc n-tiles per chunk
#define NCHUNK  (NNT / NTPC)         // 5
#define NT21    ((MAXB + 20) / 21)   // 781 gemm1 tiles (21 b's each)

// Scratch (device globals — no allocation allowed)
__device__ float g_A    [NNODE * NNODE];
__device__ uint4 g_Arec [NMT * A_RECS];
__device__ uint4 g_Brec [NNT * B_RECS];
__device__ uint4 g_AGrec[AG_RECS];
__device__ uint4 g_Zrec [(size_t)NT21 * B_RECS];
__device__ uint4 g_Trec [NMT * B_RECS];
__device__ float g_T    [MAXB * KP];     // T[b][96]

// ===========================================================================
// Helpers
// ===========================================================================
__device__ __forceinline__ u32 smem_u32(const void* p) {
    u32 a;
    asm("{ .reg .u64 t; cvta.to.shared.u64 t, %1; cvt.u32.u64 %0, t; }"
        : "=r"(a) : "l"(p));
    return a;
}
__device__ __forceinline__ void cp16(u32 dst, const void* src) {
    asm volatile("cp.async.cg.shared.global [%0], [%1], 16;"
                 :: "r"(dst), "l"(src) : "memory");
}
__device__ __forceinline__ u16 bf16bits(float f) {
    __nv_bfloat16 h = __float2bfloat16_rn(f);
    return *(u16*)&h;
}
__device__ __forceinline__ uint4 pack_rec(float f0, float f1, float f2, float f3) {
    u16 h0 = bf16bits(f0), h1 = bf16bits(f1), h2 = bf16bits(f2), h3 = bf16bits(f3);
    uint4 v;
    v.x = (u32)h0 | ((u32)h1 << 16);
    v.y = (u32)h2 | ((u32)h3 << 16);
    float l0 = f0 - __bfloat162float(*(__nv_bfloat16*)&h0);
    float l1 = f1 - __bfloat162float(*(__nv_bfloat16*)&h1);
    float l2 = f2 - __bfloat162float(*(__nv_bfloat16*)&h2);
    float l3 = f3 - __bfloat162float(*(__nv_bfloat16*)&h3);
    v.z = (u32)bf16bits(l0) | ((u32)bf16bits(l1) << 16);
    v.w = (u32)bf16bits(l2) | ((u32)bf16bits(l3) << 16);
    return v;
}

__device__ __forceinline__ void mma_bf16(float& d0, float& d1, float& d2, float& d3,
                                         u32 a0, u32 a1, u32 a2, u32 a3,
                                         u32 b0, u32 b1) {
    asm volatile(
        "mma.sync.aligned.m16n8k16.row.col.f32.bf16.bf16.f32 "
        "{%0,%1,%2,%3}, {%4,%5,%6,%7}, {%8,%9}, {%0,%1,%2,%3};"
        : "+f"(d0), "+f"(d1), "+f"(d2), "+f"(d3)
        : "r"(a0), "r"(a1), "r"(a2), "r"(a3), "r"(b0), "r"(b1));
}

// ===========================================================================
// build dense normalized adjacency (single block)
// ===========================================================================
__global__ void build_graph_kernel(const int* __restrict__ ei,
                                   const float* __restrict__ ew, int E) {
    __shared__ float deg[NNODE];
    __shared__ float dinv[NNODE];
    int t = threadIdx.x;
    for (int i = t; i < NNODE; i += blockDim.x) deg[i] = 1.0f;
    __syncthreads();
    for (int e = t; e < E; e += blockDim.x)
        atomicAdd(&deg[ei[E + e]], ew[e]);
    __syncthreads();
    for (int i = t; i < NNODE; i += blockDim.x)
        dinv[i] = (deg[i] > 0.0f) ? rsqrtf(deg[i]) : 0.0f;
    for (int i = t; i < NNODE * NNODE; i += blockDim.x) g_A[i] = 0.0f;
    __syncthreads();
    for (int e = t; e < E; e += blockDim.x) {
        int s = ei[e];
        int d = ei[E + e];
        atomicAdd(&g_A[d * NNODE + s], dinv[s] * ew[e] * dinv[d]);
    }
    for (int i = t; i < NNODE; i += blockDim.x)
        atomicAdd(&g_A[i * NNODE + i], dinv[i] * dinv[i]);
}

// ===========================================================================
// adjacency -> 96x96 A-fragment records
// ===========================================================================
__global__ void repack_ag_kernel() {
    int r = blockIdx.x * 256 + threadIdx.x;
    if (r >= AG_RECS) return;
    int lane = r & 31;
    int rc   = (r >> 5) & 1;
    int rest = r >> 6;
    int s    = rest % NS;
    int mf   = rest / NS;
    int m  = mf * 16 + rc * 8 + (lane >> 2);
    int k0 = s * 16 + 2 * (lane & 3);
    float f[4];
    #pragma unroll
    for (int j = 0; j < 4; j++) {
        int k = k0 + (j >> 1) * 8 + (j & 1);
        f[j] = (m < NNODE && k < NNODE) ? g_A[m * NNODE + k] : 0.0f;
    }
    g_AGrec[r] = pack_rec(f[0], f[1], f[2], f[3]);
}

// ===========================================================================
// Wfc -> B fragment records, with column permutation for STG.128 epilogue
// ===========================================================================
__global__ void repack_b_kernel(const float* __restrict__ Wfc) {
    int rr = blockIdx.x * 256 + threadIdx.x;
    int ntile = blockIdx.y;
    int lane = rr & 31;
    int rest = rr >> 5;
    int s    = rest % NS;
    int nf   = rest / NS;
    int g    = lane >> 2;
    int n_phys = 16 * (nf >> 1) + 4 * (g >> 1) + 2 * (nf & 1) + (g & 1);
    int n  = ntile * 128 + n_phys;
    int k0 = s * 16 + 2 * (lane & 3);
    const float* src = Wfc + (size_t)n * NNODE;
    float f[4];
    #pragma unroll
    for (int j = 0; j < 4; j++) {
        int k = k0 + (j >> 1) * 8 + (j & 1);
        f[j] = (k < NNODE) ? src[k] : 0.0f;
    }
    g_Brec[ntile * B_RECS + rr] = pack_rec(f[0], f[1], f[2], f[3]);
}

// ===========================================================================
// xz: Z records for 126-col (21-batch) tiles
// ===========================================================================
#define XZ_SMEM (21 * NNODE * 6 * 4)   // 47376 bytes

__global__ void __launch_bounds__(256)
xz_kernel(const float* __restrict__ feat, const float* __restrict__ W1, int B) {
    extern __shared__ float xws[];
    __shared__ float w1s[18];
    const int tid = threadIdx.x;
    const int bstart = blockIdx.x * 21;

    if (tid < 18) w1s[tid] = W1[tid];
    __syncthreads();

    for (int idx = tid; idx < 21 * NNODE; idx += 256) {
        int bl = idx / NNODE, j = idx - bl * NNODE;
        int b = bstart + bl;
        float x0 = 0, x1 = 0, x2 = 0;
        if (b < B) {
            const float* p = feat + (size_t)b * (NNODE * 3) + j * 3;
            x0 = p[0]; x1 = p[1]; x2 = p[2];
        }
        float* o = xws + (bl * NNODE + j) * 6;
        #pragma unroll
        for (int c = 0; c < 6; c++)
            o[c] = x0 * w1s[c] + x1 * w1s[6 + c] + x2 * w1s[12 + c];
    }
    __syncthreads();

    for (int r = tid; r < B_RECS; r += 256) {
        int lane = r & 31;
        int s    = (r >> 5) % NS;
        int nf   = r / (NS * 32);
        int col  = nf * 8 + (lane >> 2);
        int k0   = s * 16 + 2 * (lane & 3);
        uint4 v = make_uint4(0, 0, 0, 0);
        if (col < 126) {
            int bl = col / 6, c = col - (col / 6) * 6;
            if (bstart + bl < B) {
                float f[4];
                #pragma unroll
                for (int jj = 0; jj < 4; jj++) {
                    int j = k0 + (jj >> 1) * 8 + (jj & 1);
                    f[jj] = (j < NNODE) ? xws[(bl * NNODE + j) * 6 + c] : 0.0f;
                }
                v = pack_rec(f[0], f[1], f[2], f[3]);
            }
        }
        g_Zrec[(size_t)blockIdx.x * B_RECS + r] = v;
    }
}

// ===========================================================================
// GEMM1 fused: C1 = A·Z, then T = sum_c tanh(C1+b1)·W2 in-block -> g_T
// ===========================================================================
#define G_SMEM ((AG_RECS + B_RECS) * 16)   // 86016

__global__ void __launch_bounds__(256, 2)
gemm1_kernel(const float* __restrict__ b1, const float* __restrict__ W2, int B) {
    extern __shared__ char sm[];
    uint4* Af = (uint4*)sm;
    uint4* Bf = (uint4*)sm + AG_RECS;
    float* Cs = (float*)sm;                 // reused after mainloop: [128][97]
    __shared__ float b1s[6], w2s[6];
    const int tid = threadIdx.x;
    const int wid = tid >> 5, lane = tid & 31;
    const int bstart = blockIdx.x * 21;

    if (tid < 6) { b1s[tid] = b1[tid]; w2s[tid] = W2[tid]; }
    {
        const u32 af = smem_u32(Af), bf = smem_u32(Bf);
        const uint4* Bsrc = g_Zrec + (size_t)blockIdx.x * B_RECS;
        #pragma unroll
        for (int r = 0; r < AG_RECS / 256; r++)
            cp16(af + (r * 256 + tid) * 16, g_AGrec + r * 256 + tid);
        #pragma unroll
        for (int r = 0; r < B_RECS / 256; r++)
            cp16(bf + (r * 256 + tid) * 16, Bsrc + r * 256 + tid);
        asm volatile("cp.async.commit_group;");
        asm volatile("cp.async.wait_group 0;" ::: "memory");
    }
    __syncthreads();

    const int mf0 = (wid & 1) * 3;
    const int nf0 = (wid >> 1) * 4;

    float acc[3][4][4];
    #pragma unroll
    for (int i = 0; i < 3; i++)
        #pragma unroll
        for (int j = 0; j < 4; j++)
            #pragma unroll
            for (int c = 0; c < 4; c++) acc[i][j][c] = 0.0f;

    #pragma unroll
    for (int s = 0; s < NS; s++) {
        uint4 ar0[3], ar1[3];
        #pragma unroll
        for (int i = 0; i < 3; i++) {
            int mf = mf0 + i;
            ar0[i] = Af[((mf * NS + s) * 2 + 0) * 32 + lane];
            ar1[i] = Af[((mf * NS + s) * 2 + 1) * 32 + lane];
        }
        #pragma unroll
        for (int j = 0; j < 4; j++) {
            uint4 br = Bf[((nf0 + j) * NS + s) * 32 + lane];
            #pragma unroll
            for (int i = 0; i < 3; i++) {
                mma_bf16(acc[i][j][0], acc[i][j][1], acc[i][j][2], acc[i][j][3],
                         ar0[i].x, ar1[i].x, ar0[i].y, ar1[i].y, br.x, br.y);
                mma_bf16(acc[i][j][0], acc[i][j][1], acc[i][j][2], acc[i][j][3],
                         ar0[i].x, ar1[i].x, ar0[i].y, ar1[i].y, br.z, br.w);
                mma_bf16(acc[i][j][0], acc[i][j][1], acc[i][j][2], acc[i][j][3],
                         ar0[i].z, ar1[i].z, ar0[i].w, ar1[i].w, br.x, br.y);
            }
        }
    }

    __syncthreads();   // staging smem dead -> reuse as Cs

    const int g = lane >> 2, t = lane & 3;
    #pragma unroll
    for (int j = 0; j < 4; j++) {
        int col = (nf0 + j) * 8 + 2 * t;
        #pragma unroll
        for (int i = 0; i < 3; i++) {
            int row = (mf0 + i) * 16 + g;
            Cs[col * 97 + row]             = acc[i][j][0];
            Cs[(col + 1) * 97 + row]       = acc[i][j][1];
            Cs[col * 97 + row + 8]         = acc[i][j][2];
            Cs[(col + 1) * 97 + row + 8]   = acc[i][j][3];
        }
    }
    __syncthreads();

    for (int idx = tid; idx < 21 * KP; idx += 256) {
        int bl = idx / KP, j = idx - bl * KP;
        int b = bstart + bl;
        if (b < B) {
            float tv = 0.0f;
            #pragma unroll
            for (int c = 0; c < 6; c++)
                tv += tanhf(Cs[(bl * 6 + c) * 97 + j] + b1s[c]) * w2s[c];
            g_T[b * KP + j] = tv;
        }
    }
}

// ===========================================================================
// repack_t: g_T -> Trec
// ===========================================================================
__global__ void repack_t_kernel(int B) {
    int rr = blockIdx.x * 256 + threadIdx.x;
    int mtile = blockIdx.y;
    int lane = rr & 31;
    int rest = rr >> 5;
    int s    = rest % NS;
    int nf   = rest / NS;
    int b  = mtile * 128 + nf * 8 + (lane >> 2);
    int k0 = s * 16 + 2 * (lane & 3);
    uint4 v = make_uint4(0, 0, 0, 0);
    if (b < B) {
        const float* p = g_T + (size_t)b * KP + k0;
        v = pack_rec(p[0], p[1], p[8], p[9]);
    }
    g_Trec[mtile * B_RECS + rr] = v;
}

// ===========================================================================
// GEMM2 fused: H = tanh(A·T + b2); emits g_Arec records directly
// ===========================================================================
__global__ void __launch_bounds__(256, 2)
gemm2_kernel(const float* __restrict__ b2, int B) {
    extern __shared__ char sm[];
    uint4* Af = (uint4*)sm;
    uint4* Bf = (uint4*)sm + AG_RECS;
    float* Hs = (float*)sm;                 // reused: [128 b][97]
    const int tid = threadIdx.x;
    const int wid = tid >> 5, lane = tid & 31;
    const int b0 = blockIdx.x * 128;

    {
        const u32 af = smem_u32(Af), bf = smem_u32(Bf);
        const uint4* Bsrc = g_Trec + (size_t)blockIdx.x * B_RECS;
        #pragma unroll
        for (int r = 0; r < AG_RECS / 256; r++)
            cp16(af + (r * 256 + tid) * 16, g_AGrec + r * 256 + tid);
        #pragma unroll
        for (int r = 0; r < B_RECS / 256; r++)
            cp16(bf + (r * 256 + tid) * 16, Bsrc + r * 256 + tid);
        asm volatile("cp.async.commit_group;");
        asm volatile("cp.async.wait_group 0;" ::: "memory");
    }
    __syncthreads();

    const int mf0 = (wid & 1) * 3;
    const int nf0 = (wid >> 1) * 4;

    float acc[3][4][4];
    #pragma unroll
    for (int i = 0; i < 3; i++)
        #pragma unroll
        for (int j = 0; j < 4; j++)
            #pragma unroll
            for (int c = 0; c < 4; c++) acc[i][j][c] = 0.0f;

    #pragma unroll
    for (int s = 0; s < NS; s++) {
        uint4 ar0[3], ar1[3];
        #pragma unroll
        for (int i = 0; i < 3; i++) {
            int mf = mf0 + i;
            ar0[i] = Af[((mf * NS + s) * 2 + 0) * 32 + lane];
            ar1[i] = Af[((mf * NS + s) * 2 + 1) * 32 + lane];
        }
        #pragma unroll
        for (int j = 0; j < 4; j++) {
            uint4 br = Bf[((nf0 + j) * NS + s) * 32 + lane];
            #pragma unroll
            for (int i = 0; i < 3; i++) {
                mma_bf16(acc[i][j][0], acc[i][j][1], acc[i][j][2], acc[i][j][3],
                         ar0[i].x, ar1[i].x, ar0[i].y, ar1[i].y, br.x, br.y);
                mma_bf16(acc[i][j][0], acc[i][j][1], acc[i][j][2], acc[i][j][3],
                         ar0[i].x, ar1[i].x, ar0[i].y, ar1[i].y, br.z, br.w);
                mma_bf16(acc[i][j][0], acc[i][j][1], acc[i][j][2], acc[i][j][3],
                         ar0[i].z, ar1[i].z, ar0[i].w, ar1[i].w, br.x, br.y);
            }
        }
    }

    __syncthreads();   // staging smem dead -> reuse as Hs

    const float b2v = b2[0];
    const int g = lane >> 2, t = lane & 3;
    #pragma unroll
    for (int j = 0; j < 4; j++) {
        int bcol = (nf0 + j) * 8 + 2 * t;
        #pragma unroll
        for (int i = 0; i < 3; i++) {
            int row = (mf0 + i) * 16 + g;
            Hs[bcol * 97 + row]           = tanhf(acc[i][j][0] + b2v);
            Hs[(bcol + 1) * 97 + row]     = tanhf(acc[i][j][1] + b2v);
            Hs[bcol * 97 + row + 8]       = tanhf(acc[i][j][2] + b2v);
            Hs[(bcol + 1) * 97 + row + 8] = tanhf(acc[i][j][3] + b2v);
        }
    }
    __syncthreads();

    for (int r = tid; r < A_RECS; r += 256) {
        int lane2 = r & 31;
        int rc    = (r >> 5) & 1;
        int rest  = r >> 6;
        int s     = rest % NS;
        int mf    = rest / NS;
        int ml = mf * 16 + rc * 8 + (lane2 >> 2);
        int k0 = s * 16 + 2 * (lane2 & 3);
        uint4 v = make_uint4(0, 0, 0, 0);
        if (b0 + ml < B) {
            const float* p = Hs + ml * 97 + k0;
            v = pack_rec(p[0], p[1], p[8], p[9]);
        }
        g_Arec[blockIdx.x * A_RECS + r] = v;
    }
}

// ===========================================================================
// FC GEMM — PERSISTENT: one block = one m-tile x 10 n-tiles.
// A-records staged once; B double-buffered with cp.async prefetch that
// overlaps the epilogue + next mainloop.
// ===========================================================================
#define FCP_SMEM ((A_RECS + 2 * B_RECS) * 16)   // 147456

__global__ void __launch_bounds__(256, 1)
fc_mma_kernel(const float* __restrict__ bfc, float* __restrict__ out, int B) {
    extern __shared__ char sm[];
    uint4* Af  = (uint4*)sm;
    uint4* Bf0 = (uint4*)sm + A_RECS;
    uint4* Bf1 = (uint4*)sm + A_RECS + B_RECS;

    const int tid  = threadIdx.x;
    const int wid  = tid >> 5;
    const int lane = tid & 31;
    const int m0   = blockIdx.y * 128;
    const int t0   = blockIdx.x * NTPC;

    const u32 af  = smem_u32(Af);
    const u32 bf0 = smem_u32(Bf0);
    const u32 bf1 = smem_u32(Bf1);

    // Prologue: A + B(t0) in group 0, B(t0+1) in group 1
    {
        const uint4* Asrc = g_Arec + (size_t)blockIdx.y * A_RECS;
        #pragma unroll
        for (int r = 0; r < A_RECS / 256; r++)
            cp16(af + (r * 256 + tid) * 16, Asrc + r * 256 + tid);
        const uint4* Bsrc = g_Brec + (size_t)t0 * B_RECS;
        #pragma unroll
        for (int r = 0; r < B_RECS / 256; r++)
            cp16(bf0 + (r * 256 + tid) * 16, Bsrc + r * 256 + tid);
        asm volatile("cp.async.commit_group;");
        const uint4* Bsrc1 = g_Brec + (size_t)(t0 + 1) * B_RECS;
        #pragma unroll
        for (int r = 0; r < B_RECS / 256; r++)
            cp16(bf1 + (r * 256 + tid) * 16, Bsrc1 + r * 256 + tid);
        asm volatile("cp.async.commit_group;");
        asm volatile("cp.async.wait_group 1;" ::: "memory");
    }
    __syncthreads();

    const int wm = wid & 3;
    const int wn = wid >> 2;
    const int mf0 = wm * 2;
    const int nf0 = wn * 8;
    const int g = lane >> 2, t = lane & 3;

    for (int it = 0; it < NTPC; it++) {
        const int buf = it & 1;
        const uint4* Bf = buf ? Bf1 : Bf0;

        float acc[2][8][4];
        #pragma unroll
        for (int i = 0; i < 2; i++)
            #pragma unroll
            for (int j = 0; j < 8; j++)
                #pragma unroll
                for (int c = 0; c < 4; c++) acc[i][j][c] = 0.0f;

        #pragma unroll
        for (int s = 0; s < NS; s++) {
            uint4 ar0[2], ar1[2];
            #pragma unroll
            for (int i = 0; i < 2; i++) {
                int mf = mf0 + i;
                ar0[i] = Af[((mf * NS + s) * 2 + 0) * 32 + lane];
                ar1[i] = Af[((mf * NS + s) * 2 + 1) * 32 + lane];
            }
            #pragma unroll
            for (int j = 0; j < 8; j++) {
                uint4 br = Bf[((nf0 + j) * NS + s) * 32 + lane];
                #pragma unroll
                for (int i = 0; i < 2; i++) {
                    mma_bf16(acc[i][j][0], acc[i][j][1], acc[i][j][2], acc[i][j][3],
                             ar0[i].x, ar1[i].x, ar0[i].y, ar1[i].y, br.x, br.y);
                    mma_bf16(acc[i][j][0], acc[i][j][1], acc[i][j][2], acc[i][j][3],
                             ar0[i].x, ar1[i].x, ar0[i].y, ar1[i].y, br.z, br.w);
                    mma_bf16(acc[i][j][0], acc[i][j][1], acc[i][j][2], acc[i][j][3],
                             ar0[i].z, ar1[i].z, ar0[i].w, ar1[i].w, br.x, br.y);
                }
            }
        }
        __syncthreads();   // all warps done reading Bf[buf]

        // Prefetch tile it+2 into the buffer just freed (overlaps epilogue)
        if (it + 2 < NTPC) {
            const u32 bfd = buf ? bf1 : bf0;
            const uint4* Bsrc = g_Brec + (size_t)(t0 + it + 2) * B_RECS;
            #pragma unroll
            for (int r = 0; r < B_RECS / 256; r++)
                cp16(bfd + (r * 256 + tid) * 16, Bsrc + r * 256 + tid);
        }
        asm volatile("cp.async.commit_group;");

        // Epilogue (permuted STG.128)
        const int n0 = (t0 + it) * 128;
        #pragma unroll
        for (int u = 0; u < 4; u++) {
            const int j0 = 2 * u, j1 = 2 * u + 1;
            const int nbase = n0 + 64 * wn + 16 * u + 4 * t;
            float4 bz = *(const float4*)(bfc + nbase);
            #pragma unroll
            for (int i = 0; i < 2; i++) {
                int mr0 = m0 + (mf0 + i) * 16 + g;
                if (mr0 < B) {
                    float4 v = make_float4(acc[i][j0][0] + bz.x, acc[i][j0][1] + bz.y,
                                           acc[i][j1][0] + bz.z, acc[i][j1][1] + bz.w);
                    *(float4*)(out + (size_t)mr0 * NOUT + nbase) = v;
                }
                int mr1 = mr0 + 8;
                if (mr1 < B) {
                    float4 v = make_float4(acc[i][j0][2] + bz.x, acc[i][j0][3] + bz.y,
                                           acc[i][j1][2] + bz.z, acc[i][j1][3] + bz.w);
                    *(float4*)(out + (size_t)mr1 * NOUT + nbase) = v;
                }
            }
        }

        asm volatile("cp.async.wait_group 1;" ::: "memory");  // B(it+1) ready
        __syncthreads();
    }
}

// ===========================================================================
// Launch
// ===========================================================================
extern "C" void kernel_launch(void* const* d_in, const int* in_sizes, int n_in,
                              void* d_out, int out_size) {
    const float* feature = (const float*)d_in[0];
    const int*   ei      = (const int*)  d_in[1];
    const float* ew      = (const float*)d_in[2];
    const float* W1      = (const float*)d_in[3];
    const float* b1      = (const float*)d_in[4];
    const float* W2      = (const float*)d_in[5];
    const float* b2      = (const float*)d_in[6];
    const float* Wfc     = (const float*)d_in[7];
    const float* bfc     = (const float*)d_in[8];
    float*       out     = (float*)d_out;

    const int B = in_sizes[0] / (NNODE * 3);
    const int E = in_sizes[1] / 2;
    const int nmt  = (B + 127) / 128;
    const int nt21 = (B + 20) / 21;

    cudaFuncSetAttribute(xz_kernel,    cudaFuncAttributeMaxDynamicSharedMemorySize, XZ_SMEM);
    cudaFuncSetAttribute(gemm1_kernel, cudaFuncAttributeMaxDynamicSharedMemorySize, G_SMEM);
    cudaFuncSetAttribute(gemm2_kernel, cudaFuncAttributeMaxDynamicSharedMemorySize, G_SMEM);
    cudaFuncSetAttribute(fc_mma_kernel,cudaFuncAttributeMaxDynamicSharedMemorySize, FCP_SMEM);

    build_graph_kernel<<<1, 256>>>(ei, ew, E);
    repack_ag_kernel<<<(AG_RECS + 255) / 256, 256>>>();

    { dim3 gb(B_RECS / 256, NNT); repack_b_kernel<<<gb, 256>>>(Wfc); }

    xz_kernel<<<nt21, 256, XZ_SMEM>>>(feature, W1, B);
    gemm1_kernel<<<nt21, 256, G_SMEM>>>(b1, W2, B);
    { dim3 gt(B_RECS / 256, nmt); repack_t_kernel<<<gt, 256>>>(B); }
    gemm2_kernel<<<nmt, 256, G_SMEM>>>(b2, B);

    dim3 grid(NCHUNK, nmt);
    fc_mma_kernel<<<grid, 256, FCP_SMEM>>>(bfc, out, B);
}

// round 16
// speedup vs baseline: 1.2367x; 1.2367x over previous
#include <cuda_runtime.h>
#include <cuda_bf16.h>
#include <math.h>

#define NNODE 94
#define MAXB  16384
#define NOUT  6400
#define KP    96
#define NS    (KP / 16)    // 6

typedef unsigned long long u64;
typedef unsigned int u32;
typedef unsigned short u16;

#define A_RECS  (8 * NS * 2 * 32)    // 3072 (fc A tile, 128 rows)
#define B_RECS  (16 * NS * 32)       // 3072 (128-col B tile)
#define AG_RECS (6 * NS * 2 * 32)    // 2304 (adjacency tile, 96 rows)
#define NMT     (MAXB / 128)         // 128
#define NNT     (NOUT / 128)         // 50

// Scratch (device globals — no allocation allowed; zero-initialized at load)
__device__ float g_A    [NNODE * NNODE];
__device__ uint4 g_Arec [NMT * A_RECS];
__device__ uint4 g_Brec [NNT * B_RECS];
__device__ uint4 g_AGrec[AG_RECS];
__device__ uint4 g_Trec [NMT * B_RECS];

// ===========================================================================
// Helpers
// ===========================================================================
__device__ __forceinline__ u32 smem_u32(const void* p) {
    u32 a;
    asm("{ .reg .u64 t; cvta.to.shared.u64 t, %1; cvt.u32.u64 %0, t; }"
        : "=r"(a) : "l"(p));
    return a;
}
__device__ __forceinline__ void cp16(u32 dst, const void* src) {
    asm volatile("cp.async.cg.shared.global [%0], [%1], 16;"
                 :: "r"(dst), "l"(src) : "memory");
}
__device__ __forceinline__ u16 bf16bits(float f) {
    __nv_bfloat16 h = __float2bfloat16_rn(f);
    return *(u16*)&h;
}
__device__ __forceinline__ uint4 pack_rec(float f0, float f1, float f2, float f3) {
    u16 h0 = bf16bits(f0), h1 = bf16bits(f1), h2 = bf16bits(f2), h3 = bf16bits(f3);
    uint4 v;
    v.x = (u32)h0 | ((u32)h1 << 16);
    v.y = (u32)h2 | ((u32)h3 << 16);
    float l0 = f0 - __bfloat162float(*(__nv_bfloat16*)&h0);
    float l1 = f1 - __bfloat162float(*(__nv_bfloat16*)&h1);
    float l2 = f2 - __bfloat162float(*(__nv_bfloat16*)&h2);
    float l3 = f3 - __bfloat162float(*(__nv_bfloat16*)&h3);
    v.z = (u32)bf16bits(l0) | ((u32)bf16bits(l1) << 16);
    v.w = (u32)bf16bits(l2) | ((u32)bf16bits(l3) << 16);
    return v;
}

__device__ __forceinline__ void mma_bf16(float& d0, float& d1, float& d2, float& d3,
                                         u32 a0, u32 a1, u32 a2, u32 a3,
                                         u32 b0, u32 b1) {
    asm volatile(
        "mma.sync.aligned.m16n8k16.row.col.f32.bf16.bf16.f32 "
        "{%0,%1,%2,%3}, {%4,%5,%6,%7}, {%8,%9}, {%0,%1,%2,%3};"
        : "+f"(d0), "+f"(d1), "+f"(d2), "+f"(d3)
        : "r"(a0), "r"(a1), "r"(a2), "r"(a3), "r"(b0), "r"(b1));
}

// ===========================================================================
// build dense normalized adjacency (single block)
// ===========================================================================
__global__ void build_graph_kernel(const int* __restrict__ ei,
                                   const float* __restrict__ ew, int E) {
    __shared__ float deg[NNODE];
    __shared__ float dinv[NNODE];
    int t = threadIdx.x;
    for (int i = t; i < NNODE; i += blockDim.x) deg[i] = 1.0f;
    __syncthreads();
    for (int e = t; e < E; e += blockDim.x)
        atomicAdd(&deg[ei[E + e]], ew[e]);
    __syncthreads();
    for (int i = t; i < NNODE; i += blockDim.x)
        dinv[i] = (deg[i] > 0.0f) ? rsqrtf(deg[i]) : 0.0f;
    for (int i = t; i < NNODE * NNODE; i += blockDim.x) g_A[i] = 0.0f;
    __syncthreads();
    for (int e = t; e < E; e += blockDim.x) {
        int s = ei[e];
        int d = ei[E + e];
        atomicAdd(&g_A[d * NNODE + s], dinv[s] * ew[e] * dinv[d]);
    }
    for (int i = t; i < NNODE; i += blockDim.x)
        atomicAdd(&g_A[i * NNODE + i], dinv[i] * dinv[i]);
}

// ===========================================================================
// adjacency -> 96x96 A-fragment records
// ===========================================================================
__global__ void repack_ag_kernel() {
    int r = blockIdx.x * 256 + threadIdx.x;
    if (r >= AG_RECS) return;
    int lane = r & 31;
    int rc   = (r >> 5) & 1;
    int rest = r >> 6;
    int s    = rest % NS;
    int mf   = rest / NS;
    int m  = mf * 16 + rc * 8 + (lane >> 2);
    int k0 = s * 16 + 2 * (lane & 3);
    float f[4];
    #pragma unroll
    for (int j = 0; j < 4; j++) {
        int k = k0 + (j >> 1) * 8 + (j & 1);
        f[j] = (m < NNODE && k < NNODE) ? g_A[m * NNODE + k] : 0.0f;
    }
    g_AGrec[r] = pack_rec(f[0], f[1], f[2], f[3]);
}

// ===========================================================================
// Wfc -> B fragment records, with column permutation for STG.128 epilogue
// ===========================================================================
__global__ void repack_b_kernel(const float* __restrict__ Wfc) {
    int rr = blockIdx.x * 256 + threadIdx.x;
    int ntile = blockIdx.y;
    int lane = rr & 31;
    int rest = rr >> 5;
    int s    = rest % NS;
    int nf   = rest / NS;
    int g    = lane >> 2;
    int n_phys = 16 * (nf >> 1) + 4 * (g >> 1) + 2 * (nf & 1) + (g & 1);
    int n  = ntile * 128 + n_phys;
    int k0 = s * 16 + 2 * (lane & 3);
    const float* src = Wfc + (size_t)n * NNODE;
    float f[4];
    #pragma unroll
    for (int j = 0; j < 4; j++) {
        int k = k0 + (j >> 1) * 8 + (j & 1);
        f[j] = (k < NNODE) ? src[k] : 0.0f;
    }
    g_Brec[ntile * B_RECS + rr] = pack_rec(f[0], f[1], f[2], f[3]);
}

// ===========================================================================
// GEMM1 FUSED: feature -> xw (smem) -> B-records (smem) -> C1 = A·Z (MMA)
//              -> T = sum_c tanh(C1+b1)·W2 -> Trec scattered to global.
// One block per 21 batch elements. No Zrec / g_T round trips.
// smem layout: [Bf 48K][xws 47.4K][Af 36.9K]; after mainloop reuse:
//   Cs = offset 0 (49.7K over dead Bf+xws head), Ts = Af region.
// ===========================================================================
#define G1_OFF_BF  0
#define G1_OFF_XWS (B_RECS * 16)                    // 49152
#define G1_OFF_AF  (G1_OFF_XWS + 21 * NNODE * 6 * 4) // 49152+47376=96528
#define G1_SMEM    (G1_OFF_AF + AG_RECS * 16)       // 133392

__global__ void __launch_bounds__(256, 1)
gemm1_kernel(const float* __restrict__ feat, const float* __restrict__ W1,
             const float* __restrict__ b1, const float* __restrict__ W2, int B) {
    extern __shared__ char sm[];
    uint4* Bf  = (uint4*)(sm + G1_OFF_BF);
    float* xws = (float*)(sm + G1_OFF_XWS);
    uint4* Af  = (uint4*)(sm + G1_OFF_AF);
    float* Cs  = (float*)sm;                 // reuse after mainloop [128][97]
    float* Ts  = (float*)(sm + G1_OFF_AF);   // reuse after mainloop [21][97]
    __shared__ float w1s[18], b1s[6], w2s[6];
    const int tid = threadIdx.x;
    const int wid = tid >> 5, lane = tid & 31;
    const int bstart = blockIdx.x * 21;

    // Start A-record staging early (overlaps all the xw work)
    {
        const u32 af = smem_u32(Af);
        #pragma unroll
        for (int r = 0; r < AG_RECS / 256; r++)
            cp16(af + (r * 256 + tid) * 16, g_AGrec + r * 256 + tid);
        asm volatile("cp.async.commit_group;");
    }
    if (tid < 18) w1s[tid] = W1[tid];
    if (tid < 6)  { b1s[tid] = b1[tid]; w2s[tid] = W2[tid]; }
    __syncthreads();

    // xw[bl][j][c] = sum_d X[b][j][d] W1[d][c]
    for (int idx = tid; idx < 21 * NNODE; idx += 256) {
        int bl = idx / NNODE, j = idx - bl * NNODE;
        int b = bstart + bl;
        float x0 = 0, x1 = 0, x2 = 0;
        if (b < B) {
            const float* p = feat + (size_t)b * (NNODE * 3) + j * 3;
            x0 = p[0]; x1 = p[1]; x2 = p[2];
        }
        float* o = xws + (bl * NNODE + j) * 6;
        #pragma unroll
        for (int c = 0; c < 6; c++)
            o[c] = x0 * w1s[c] + x1 * w1s[6 + c] + x2 * w1s[12 + c];
    }
    __syncthreads();

    // Pack Z records smem->smem
    for (int r = tid; r < B_RECS; r += 256) {
        int lane2 = r & 31;
        int s     = (r >> 5) % NS;
        int nf    = r / (NS * 32);
        int col   = nf * 8 + (lane2 >> 2);
        int k0    = s * 16 + 2 * (lane2 & 3);
        uint4 v = make_uint4(0, 0, 0, 0);
        if (col < 126) {
            int bl = col / 6, c = col - (col / 6) * 6;
            if (bstart + bl < B) {
                float f[4];
                #pragma unroll
                for (int jj = 0; jj < 4; jj++) {
                    int j = k0 + (jj >> 1) * 8 + (jj & 1);
                    f[jj] = (j < NNODE) ? xws[(bl * NNODE + j) * 6 + c] : 0.0f;
                }
                v = pack_rec(f[0], f[1], f[2], f[3]);
            }
        }
        Bf[r] = v;
    }
    asm volatile("cp.async.wait_group 0;" ::: "memory");
    __syncthreads();

    const int mf0 = (wid & 1) * 3;
    const int nf0 = (wid >> 1) * 4;

    float acc[3][4][4];
    #pragma unroll
    for (int i = 0; i < 3; i++)
        #pragma unroll
        for (int j = 0; j < 4; j++)
            #pragma unroll
            for (int c = 0; c < 4; c++) acc[i][j][c] = 0.0f;

    #pragma unroll
    for (int s = 0; s < NS; s++) {
        uint4 ar0[3], ar1[3];
        #pragma unroll
        for (int i = 0; i < 3; i++) {
            int mf = mf0 + i;
            ar0[i] = Af[((mf * NS + s) * 2 + 0) * 32 + lane];
            ar1[i] = Af[((mf * NS + s) * 2 + 1) * 32 + lane];
        }
        #pragma unroll
        for (int j = 0; j < 4; j++) {
            uint4 br = Bf[((nf0 + j) * NS + s) * 32 + lane];
            #pragma unroll
            for (int i = 0; i < 3; i++) {
                mma_bf16(acc[i][j][0], acc[i][j][1], acc[i][j][2], acc[i][j][3],
                         ar0[i].x, ar1[i].x, ar0[i].y, ar1[i].y, br.x, br.y);
                mma_bf16(acc[i][j][0], acc[i][j][1], acc[i][j][2], acc[i][j][3],
                         ar0[i].x, ar1[i].x, ar0[i].y, ar1[i].y, br.z, br.w);
                mma_bf16(acc[i][j][0], acc[i][j][1], acc[i][j][2], acc[i][j][3],
                         ar0[i].z, ar1[i].z, ar0[i].w, ar1[i].w, br.x, br.y);
            }
        }
    }
    __syncthreads();   // Bf/xws/Af dead -> reuse as Cs/Ts

    const int g = lane >> 2, t = lane & 3;
    #pragma unroll
    for (int j = 0; j < 4; j++) {
        int col = (nf0 + j) * 8 + 2 * t;
        #pragma unroll
        for (int i = 0; i < 3; i++) {
            int row = (mf0 + i) * 16 + g;
            Cs[col * 97 + row]             = acc[i][j][0];
            Cs[(col + 1) * 97 + row]       = acc[i][j][1];
            Cs[col * 97 + row + 8]         = acc[i][j][2];
            Cs[(col + 1) * 97 + row + 8]   = acc[i][j][3];
        }
    }
    __syncthreads();

    // T[bl][j] = sum_c tanh(C1 + b1)*W2   (rows 94/95 multiplied by zero later)
    for (int idx = tid; idx < 21 * KP; idx += 256) {
        int bl = idx / KP, j = idx - bl * KP;
        float tv = 0.0f;
        #pragma unroll
        for (int c = 0; c < 6; c++)
            tv += tanhf(Cs[(bl * 6 + c) * 97 + j] + b1s[c]) * w2s[c];
        Ts[bl * 97 + j] = tv;
    }
    __syncthreads();

    // Scatter Trec records (each uint4 belongs to exactly one b)
    for (int r = tid; r < 21 * 24; r += 256) {
        int bl = r / 24, q = r - bl * 24;
        int s = q >> 2, t2 = q & 3;
        int b = bstart + bl;
        if (b < B) {
            int k0 = s * 16 + 2 * t2;
            uint4 v = pack_rec(Ts[bl * 97 + k0],     Ts[bl * 97 + k0 + 1],
                               Ts[bl * 97 + k0 + 8], Ts[bl * 97 + k0 + 9]);
            int tile = b >> 7;
            int nf   = (b >> 3) & 15;
            int gg   = b & 7;
            g_Trec[(size_t)tile * B_RECS + (nf * NS + s) * 32 + (gg * 4 + t2)] = v;
        }
    }
}

// ===========================================================================
// GEMM2 fused: H = tanh(A·T + b2); emits g_Arec records directly
// ===========================================================================
#define G_SMEM ((AG_RECS + B_RECS) * 16)   // 86016

__global__ void __launch_bounds__(256, 2)
gemm2_kernel(const float* __restrict__ b2, int B) {
    extern __shared__ char sm[];
    uint4* Af = (uint4*)sm;
    uint4* Bf = (uint4*)sm + AG_RECS;
    float* Hs = (float*)sm;                 // reused: [128 b][97]
    const int tid = threadIdx.x;
    const int wid = tid >> 5, lane = tid & 31;
    const int b0 = blockIdx.x * 128;

    {
        const u32 af = smem_u32(Af), bf = smem_u32(Bf);
        const uint4* Bsrc = g_Trec + (size_t)blockIdx.x * B_RECS;
        #pragma unroll
        for (int r = 0; r < AG_RECS / 256; r++)
            cp16(af + (r * 256 + tid) * 16, g_AGrec + r * 256 + tid);
        #pragma unroll
        for (int r = 0; r < B_RECS / 256; r++)
            cp16(bf + (r * 256 + tid) * 16, Bsrc + r * 256 + tid);
        asm volatile("cp.async.commit_group;");
        asm volatile("cp.async.wait_group 0;" ::: "memory");
    }
    __syncthreads();

    const int mf0 = (wid & 1) * 3;
    const int nf0 = (wid >> 1) * 4;

    float acc[3][4][4];
    #pragma unroll
    for (int i = 0; i < 3; i++)
        #pragma unroll
        for (int j = 0; j < 4; j++)
            #pragma unroll
            for (int c = 0; c < 4; c++) acc[i][j][c] = 0.0f;

    #pragma unroll
    for (int s = 0; s < NS; s++) {
        uint4 ar0[3], ar1[3];
        #pragma unroll
        for (int i = 0; i < 3; i++) {
            int mf = mf0 + i;
            ar0[i] = Af[((mf * NS + s) * 2 + 0) * 32 + lane];
            ar1[i] = Af[((mf * NS + s) * 2 + 1) * 32 + lane];
        }
        #pragma unroll
        for (int j = 0; j < 4; j++) {
            uint4 br = Bf[((nf0 + j) * NS + s) * 32 + lane];
            #pragma unroll
            for (int i = 0; i < 3; i++) {
                mma_bf16(acc[i][j][0], acc[i][j][1], acc[i][j][2], acc[i][j][3],
                         ar0[i].x, ar1[i].x, ar0[i].y, ar1[i].y, br.x, br.y);
                mma_bf16(acc[i][j][0], acc[i][j][1], acc[i][j][2], acc[i][j][3],
                         ar0[i].x, ar1[i].x, ar0[i].y, ar1[i].y, br.z, br.w);
                mma_bf16(acc[i][j][0], acc[i][j][1], acc[i][j][2], acc[i][j][3],
                         ar0[i].z, ar1[i].z, ar0[i].w, ar1[i].w, br.x, br.y);
            }
        }
    }

    __syncthreads();   // staging smem dead -> reuse as Hs

    const float b2v = b2[0];
    const int g = lane >> 2, t = lane & 3;
    #pragma unroll
    for (int j = 0; j < 4; j++) {
        int bcol = (nf0 + j) * 8 + 2 * t;
        #pragma unroll
        for (int i = 0; i < 3; i++) {
            int row = (mf0 + i) * 16 + g;
            Hs[bcol * 97 + row]           = tanhf(acc[i][j][0] + b2v);
            Hs[(bcol + 1) * 97 + row]     = tanhf(acc[i][j][1] + b2v);
            Hs[bcol * 97 + row + 8]       = tanhf(acc[i][j][2] + b2v);
            Hs[(bcol + 1) * 97 + row + 8] = tanhf(acc[i][j][3] + b2v);
        }
    }
    __syncthreads();

    for (int r = tid; r < A_RECS; r += 256) {
        int lane2 = r & 31;
        int rc    = (r >> 5) & 1;
        int rest  = r >> 6;
        int s     = rest % NS;
        int mf    = rest / NS;
        int ml = mf * 16 + rc * 8 + (lane2 >> 2);
        int k0 = s * 16 + 2 * (lane2 & 3);
        uint4 v = make_uint4(0, 0, 0, 0);
        if (b0 + ml < B) {
            const float* p = Hs + ml * 97 + k0;
            v = pack_rec(p[0], p[1], p[8], p[9]);
        }
        g_Arec[blockIdx.x * A_RECS + r] = v;
    }
}

// ===========================================================================
// FC GEMM — reverted to R14 (proven fastest): per-tile blocks, 2/SM,
// cp.async staging, permuted STG.128 epilogue
// ===========================================================================
#define FC_SMEM ((A_RECS + B_RECS) * 16)  // 98304

__global__ void __launch_bounds__(256, 2)
fc_mma_kernel(const float* __restrict__ bfc, float* __restrict__ out, int B) {
    extern __shared__ char sm[];
    uint4* Af = (uint4*)sm;
    uint4* Bf = (uint4*)sm + A_RECS;

    const int tid  = threadIdx.x;
    const int wid  = tid >> 5;
    const int lane = tid & 31;
    const int m0   = blockIdx.y * 128;
    const int n0   = blockIdx.x * 128;

    {
        const u32 af = smem_u32(Af);
        const u32 bf = smem_u32(Bf);
        const uint4* Asrc = g_Arec + (size_t)blockIdx.y * A_RECS;
        const uint4* Bsrc = g_Brec + (size_t)blockIdx.x * B_RECS;
        #pragma unroll
        for (int r = 0; r < A_RECS / 256; r++)
            cp16(af + (r * 256 + tid) * 16, Asrc + r * 256 + tid);
        #pragma unroll
        for (int r = 0; r < B_RECS / 256; r++)
            cp16(bf + (r * 256 + tid) * 16, Bsrc + r * 256 + tid);
        asm volatile("cp.async.commit_group;");
        asm volatile("cp.async.wait_group 0;" ::: "memory");
    }
    __syncthreads();

    const int wm = wid & 3;
    const int wn = wid >> 2;
    const int mf0 = wm * 2;
    const int nf0 = wn * 8;

    float acc[2][8][4];
    #pragma unroll
    for (int i = 0; i < 2; i++)
        #pragma unroll
        for (int j = 0; j < 8; j++)
            #pragma unroll
            for (int c = 0; c < 4; c++) acc[i][j][c] = 0.0f;

    #pragma unroll
    for (int s = 0; s < NS; s++) {
        uint4 ar0[2], ar1[2];
        #pragma unroll
        for (int i = 0; i < 2; i++) {
            int mf = mf0 + i;
            ar0[i] = Af[((mf * NS + s) * 2 + 0) * 32 + lane];
            ar1[i] = Af[((mf * NS + s) * 2 + 1) * 32 + lane];
        }
        #pragma unroll
        for (int j = 0; j < 8; j++) {
            uint4 br = Bf[((nf0 + j) * NS + s) * 32 + lane];
            #pragma unroll
            for (int i = 0; i < 2; i++) {
                mma_bf16(acc[i][j][0], acc[i][j][1], acc[i][j][2], acc[i][j][3],
                         ar0[i].x, ar1[i].x, ar0[i].y, ar1[i].y, br.x, br.y);
                mma_bf16(acc[i][j][0], acc[i][j][1], acc[i][j][2], acc[i][j][3],
                         ar0[i].x, ar1[i].x, ar0[i].y, ar1[i].y, br.z, br.w);
                mma_bf16(acc[i][j][0], acc[i][j][1], acc[i][j][2], acc[i][j][3],
                         ar0[i].z, ar1[i].z, ar0[i].w, ar1[i].w, br.x, br.y);
            }
        }
    }

    // ---- Epilogue: permuted layout -> float4 stores ----
    const int g = lane >> 2, t = lane & 3;
    #pragma unroll
    for (int u = 0; u < 4; u++) {
        const int j0 = 2 * u, j1 = 2 * u + 1;
        const int nbase = n0 + 64 * wn + 16 * u + 4 * t;
        float4 bz = *(const float4*)(bfc + nbase);
        #pragma unroll
        for (int i = 0; i < 2; i++) {
            int mr0 = m0 + (mf0 + i) * 16 + g;
            if (mr0 < B) {
                float4 v = make_float4(acc[i][j0][0] + bz.x, acc[i][j0][1] + bz.y,
                                       acc[i][j1][0] + bz.z, acc[i][j1][1] + bz.w);
                *(float4*)(out + (size_t)mr0 * NOUT + nbase) = v;
            }
            int mr1 = mr0 + 8;
            if (mr1 < B) {
                float4 v = make_float4(acc[i][j0][2] + bz.x, acc[i][j0][3] + bz.y,
                                       acc[i][j1][2] + bz.z, acc[i][j1][3] + bz.w);
                *(float4*)(out + (size_t)mr1 * NOUT + nbase) = v;
            }
        }
    }
}

// ===========================================================================
// Launch
// ===========================================================================
extern "C" void kernel_launch(void* const* d_in, const int* in_sizes, int n_in,
                              void* d_out, int out_size) {
    const float* feature = (const float*)d_in[0];
    const int*   ei      = (const int*)  d_in[1];
    const float* ew      = (const float*)d_in[2];
    const float* W1      = (const float*)d_in[3];
    const float* b1      = (const float*)d_in[4];
    const float* W2      = (const float*)d_in[5];
    const float* b2      = (const float*)d_in[6];
    const float* Wfc     = (const float*)d_in[7];
    const float* bfc     = (const float*)d_in[8];
    float*       out     = (float*)d_out;

    const int B = in_sizes[0] / (NNODE * 3);
    const int E = in_sizes[1] / 2;
    const int nmt  = (B + 127) / 128;
    const int nt21 = (B + 20) / 21;

    cudaFuncSetAttribute(gemm1_kernel, cudaFuncAttributeMaxDynamicSharedMemorySize, G1_SMEM);
    cudaFuncSetAttribute(gemm2_kernel, cudaFuncAttributeMaxDynamicSharedMemorySize, G_SMEM);
    cudaFuncSetAttribute(fc_mma_kernel,cudaFuncAttributeMaxDynamicSharedMemorySize, FC_SMEM);

    build_graph_kernel<<<1, 256>>>(ei, ew, E);
    repack_ag_kernel<<<(AG_RECS + 255) / 256, 256>>>();

    { dim3 gb(B_RECS / 256, NNT); repack_b_kernel<<<gb, 256>>>(Wfc); }

    gemm1_kernel<<<nt21, 256, G1_SMEM>>>(feature, W1, b1, W2, B);
    gemm2_kernel<<<nmt, 256, G_SMEM>>>(b2, B);

    dim3 grid(NNT, nmt);
    fc_mma_kernel<<<grid, 256, FC_SMEM>>>(bfc, out, B);
}

// round 17
// speedup vs baseline: 1.3689x; 1.1069x over previous
#include <cuda_runtime.h>
#include <cuda_bf16.h>
#include <math.h>

#define NNODE 94
#define MAXB  16384
#define NOUT  6400
#define KP    96
#define NS    (KP / 16)    // 6

typedef unsigned long long u64;
typedef unsigned int u32;
typedef unsigned short u16;

#define A_RECS  (8 * NS * 2 * 32)    // 3072 (fc A tile, 128 rows)
#define B_RECS  (16 * NS * 32)       // 3072 (128-col B tile)
#define AG_RECS (6 * NS * 2 * 32)    // 2304 (adjacency tile, 96 rows)
#define NMT     (MAXB / 128)         // 128
#define NNT     (NOUT / 128)         // 50

// Scratch (device globals — no allocation allowed; zero-initialized at load)
__device__ float g_A    [NNODE * NNODE];
__device__ uint4 g_Arec [NMT * A_RECS];
__device__ uint4 g_Brec [NNT * B_RECS];
__device__ uint4 g_AGrec[AG_RECS];
__device__ uint4 g_Trec [NMT * B_RECS];

// ===========================================================================
// Helpers
// ===========================================================================
__device__ __forceinline__ u32 smem_u32(const void* p) {
    u32 a;
    asm("{ .reg .u64 t; cvta.to.shared.u64 t, %1; cvt.u32.u64 %0, t; }"
        : "=r"(a) : "l"(p));
    return a;
}
__device__ __forceinline__ void cp16(u32 dst, const void* src) {
    asm volatile("cp.async.cg.shared.global [%0], [%1], 16;"
                 :: "r"(dst), "l"(src) : "memory");
}
__device__ __forceinline__ u16 bf16bits(float f) {
    __nv_bfloat16 h = __float2bfloat16_rn(f);
    return *(u16*)&h;
}
__device__ __forceinline__ uint4 pack_rec(float f0, float f1, float f2, float f3) {
    u16 h0 = bf16bits(f0), h1 = bf16bits(f1), h2 = bf16bits(f2), h3 = bf16bits(f3);
    uint4 v;
    v.x = (u32)h0 | ((u32)h1 << 16);
    v.y = (u32)h2 | ((u32)h3 << 16);
    float l0 = f0 - __bfloat162float(*(__nv_bfloat16*)&h0);
    float l1 = f1 - __bfloat162float(*(__nv_bfloat16*)&h1);
    float l2 = f2 - __bfloat162float(*(__nv_bfloat16*)&h2);
    float l3 = f3 - __bfloat162float(*(__nv_bfloat16*)&h3);
    v.z = (u32)bf16bits(l0) | ((u32)bf16bits(l1) << 16);
    v.w = (u32)bf16bits(l2) | ((u32)bf16bits(l3) << 16);
    return v;
}

__device__ __forceinline__ void mma_bf16(float& d0, float& d1, float& d2, float& d3,
                                         u32 a0, u32 a1, u32 a2, u32 a3,
                                         u32 b0, u32 b1) {
    asm volatile(
        "mma.sync.aligned.m16n8k16.row.col.f32.bf16.bf16.f32 "
        "{%0,%1,%2,%3}, {%4,%5,%6,%7}, {%8,%9}, {%0,%1,%2,%3};"
        : "+f"(d0), "+f"(d1), "+f"(d2), "+f"(d3)
        : "r"(a0), "r"(a1), "r"(a2), "r"(a3), "r"(b0), "r"(b1));
}

// ===========================================================================
// build dense normalized adjacency (single block)
// ===========================================================================
__global__ void build_graph_kernel(const int* __restrict__ ei,
                                   const float* __restrict__ ew, int E) {
    __shared__ float deg[NNODE];
    __shared__ float dinv[NNODE];
    int t = threadIdx.x;
    for (int i = t; i < NNODE; i += blockDim.x) deg[i] = 1.0f;
    __syncthreads();
    for (int e = t; e < E; e += blockDim.x)
        atomicAdd(&deg[ei[E + e]], ew[e]);
    __syncthreads();
    for (int i = t; i < NNODE; i += blockDim.x)
        dinv[i] = (deg[i] > 0.0f) ? rsqrtf(deg[i]) : 0.0f;
    for (int i = t; i < NNODE * NNODE; i += blockDim.x) g_A[i] = 0.0f;
    __syncthreads();
    for (int e = t; e < E; e += blockDim.x) {
        int s = ei[e];
        int d = ei[E + e];
        atomicAdd(&g_A[d * NNODE + s], dinv[s] * ew[e] * dinv[d]);
    }
    for (int i = t; i < NNODE; i += blockDim.x)
        atomicAdd(&g_A[i * NNODE + i], dinv[i] * dinv[i]);
}

// ===========================================================================
// adjacency -> 96x96 A-fragment records
// ===========================================================================
__global__ void repack_ag_kernel() {
    int r = blockIdx.x * 256 + threadIdx.x;
    if (r >= AG_RECS) return;
    int lane = r & 31;
    int rc   = (r >> 5) & 1;
    int rest = r >> 6;
    int s    = rest % NS;
    int mf   = rest / NS;
    int m  = mf * 16 + rc * 8 + (lane >> 2);
    int k0 = s * 16 + 2 * (lane & 3);
    float f[4];
    #pragma unroll
    for (int j = 0; j < 4; j++) {
        int k = k0 + (j >> 1) * 8 + (j & 1);
        f[j] = (m < NNODE && k < NNODE) ? g_A[m * NNODE + k] : 0.0f;
    }
    g_AGrec[r] = pack_rec(f[0], f[1], f[2], f[3]);
}

// ===========================================================================
// Wfc -> B fragment records, with column permutation for STG.128 epilogue
// ===========================================================================
__global__ void repack_b_kernel(const float* __restrict__ Wfc) {
    int rr = blockIdx.x * 256 + threadIdx.x;
    int ntile = blockIdx.y;
    int lane = rr & 31;
    int rest = rr >> 5;
    int s    = rest % NS;
    int nf   = rest / NS;
    int g    = lane >> 2;
    int n_phys = 16 * (nf >> 1) + 4 * (g >> 1) + 2 * (nf & 1) + (g & 1);
    int n  = ntile * 128 + n_phys;
    int k0 = s * 16 + 2 * (lane & 3);
    const float* src = Wfc + (size_t)n * NNODE;
    float f[4];
    #pragma unroll
    for (int j = 0; j < 4; j++) {
        int k = k0 + (j >> 1) * 8 + (j & 1);
        f[j] = (k < NNODE) ? src[k] : 0.0f;
    }
    g_Brec[ntile * B_RECS + rr] = pack_rec(f[0], f[1], f[2], f[3]);
}

// ===========================================================================
// GEMM1 FUSED v2: feature (raw, 23.2KB smem) -> B-records (W1 dot folded
// into packing) -> C1 = A·Z (MMA) -> T = sum_c tanh(C1+b1)·W2 -> Trec scatter.
// One block per 21 batch elements. smem ~109.7KB -> 2 blocks/SM.
// ===========================================================================
#define G1_OFF_BF   0
#define G1_OFF_FEAT (B_RECS * 16)                       // 49152
#define G1_FEAT_SZ  (21 * NNODE * 3 * 4)                // 23688
#define G1_OFF_AF   ((G1_OFF_FEAT + G1_FEAT_SZ + 15) & ~15)  // 72848
#define G1_SMEM     (G1_OFF_AF + AG_RECS * 16)          // 109712

__global__ void __launch_bounds__(256, 2)
gemm1_kernel(const float* __restrict__ feat, const float* __restrict__ W1,
             const float* __restrict__ b1, const float* __restrict__ W2, int B) {
    extern __shared__ char sm[];
    uint4* Bf  = (uint4*)(sm + G1_OFF_BF);
    float* fb  = (float*)(sm + G1_OFF_FEAT);
    uint4* Af  = (uint4*)(sm + G1_OFF_AF);
    float* Cs  = (float*)sm;                 // reuse after mainloop [128][97]
    float* Ts  = (float*)(sm + G1_OFF_AF);   // reuse after mainloop [21][97]
    __shared__ float w1s[18], b1s[6], w2s[6];
    const int tid = threadIdx.x;
    const int wid = tid >> 5, lane = tid & 31;
    const int bstart = blockIdx.x * 21;

    // A-record staging overlaps feature load
    {
        const u32 af = smem_u32(Af);
        #pragma unroll
        for (int r = 0; r < AG_RECS / 256; r++)
            cp16(af + (r * 256 + tid) * 16, g_AGrec + r * 256 + tid);
        asm volatile("cp.async.commit_group;");
    }
    if (tid < 18) w1s[tid] = W1[tid];
    if (tid < 6)  { b1s[tid] = b1[tid]; w2s[tid] = W2[tid]; }

    // Load raw features [21][94][3] (coalesced); zero-fill past B
    {
        const int nfl = 21 * NNODE * 3;      // 5922 floats
        const float* src = feat + (size_t)bstart * (NNODE * 3);
        const int avail = (B - bstart) * (NNODE * 3);
        for (int i = tid; i < nfl; i += 256)
            fb[i] = (i < avail) ? src[i] : 0.0f;
    }
    __syncthreads();

    // Pack Z records, folding in the X@W1 dot
    for (int r = tid; r < B_RECS; r += 256) {
        int lane2 = r & 31;
        int s     = (r >> 5) % NS;
        int nf    = r / (NS * 32);
        int col   = nf * 8 + (lane2 >> 2);
        int k0    = s * 16 + 2 * (lane2 & 3);
        uint4 v = make_uint4(0, 0, 0, 0);
        if (col < 126) {
            int bl = col / 6, c = col - (col / 6) * 6;
            float f[4];
            #pragma unroll
            for (int jj = 0; jj < 4; jj++) {
                int j = k0 + (jj >> 1) * 8 + (jj & 1);
                float x = 0.0f;
                if (j < NNODE) {
                    const float* p = fb + (bl * NNODE + j) * 3;
                    x = p[0] * w1s[c] + p[1] * w1s[6 + c] + p[2] * w1s[12 + c];
                }
                f[jj] = x;
            }
            v = pack_rec(f[0], f[1], f[2], f[3]);
        }
        Bf[r] = v;
    }
    asm volatile("cp.async.wait_group 0;" ::: "memory");
    __syncthreads();

    const int mf0 = (wid & 1) * 3;
    const int nf0 = (wid >> 1) * 4;

    float acc[3][4][4];
    #pragma unroll
    for (int i = 0; i < 3; i++)
        #pragma unroll
        for (int j = 0; j < 4; j++)
            #pragma unroll
            for (int c = 0; c < 4; c++) acc[i][j][c] = 0.0f;

    #pragma unroll
    for (int s = 0; s < NS; s++) {
        uint4 ar0[3], ar1[3];
        #pragma unroll
        for (int i = 0; i < 3; i++) {
            int mf = mf0 + i;
            ar0[i] = Af[((mf * NS + s) * 2 + 0) * 32 + lane];
            ar1[i] = Af[((mf * NS + s) * 2 + 1) * 32 + lane];
        }
        #pragma unroll
        for (int j = 0; j < 4; j++) {
            uint4 br = Bf[((nf0 + j) * NS + s) * 32 + lane];
            #pragma unroll
            for (int i = 0; i < 3; i++) {
                mma_bf16(acc[i][j][0], acc[i][j][1], acc[i][j][2], acc[i][j][3],
                         ar0[i].x, ar1[i].x, ar0[i].y, ar1[i].y, br.x, br.y);
                mma_bf16(acc[i][j][0], acc[i][j][1], acc[i][j][2], acc[i][j][3],
                         ar0[i].x, ar1[i].x, ar0[i].y, ar1[i].y, br.z, br.w);
                mma_bf16(acc[i][j][0], acc[i][j][1], acc[i][j][2], acc[i][j][3],
                         ar0[i].z, ar1[i].z, ar0[i].w, ar1[i].w, br.x, br.y);
            }
        }
    }
    __syncthreads();   // Bf/fb/Af dead -> reuse as Cs/Ts

    const int g = lane >> 2, t = lane & 3;
    #pragma unroll
    for (int j = 0; j < 4; j++) {
        int col = (nf0 + j) * 8 + 2 * t;
        #pragma unroll
        for (int i = 0; i < 3; i++) {
            int row = (mf0 + i) * 16 + g;
            Cs[col * 97 + row]             = acc[i][j][0];
            Cs[(col + 1) * 97 + row]       = acc[i][j][1];
            Cs[col * 97 + row + 8]         = acc[i][j][2];
            Cs[(col + 1) * 97 + row + 8]   = acc[i][j][3];
        }
    }
    __syncthreads();

    // T[bl][j] = sum_c tanh(C1 + b1)*W2  (rows 94/95 hit zero adjacency later)
    for (int idx = tid; idx < 21 * KP; idx += 256) {
        int bl = idx / KP, j = idx - bl * KP;
        float tv = 0.0f;
        #pragma unroll
        for (int c = 0; c < 6; c++)
            tv += tanhf(Cs[(bl * 6 + c) * 97 + j] + b1s[c]) * w2s[c];
        Ts[bl * 97 + j] = tv;
    }
    __syncthreads();

    // Scatter Trec records (each uint4 belongs to exactly one b)
    for (int r = tid; r < 21 * 24; r += 256) {
        int bl = r / 24, q = r - bl * 24;
        int s = q >> 2, t2 = q & 3;
        int b = bstart + bl;
        if (b < B) {
            int k0 = s * 16 + 2 * t2;
            uint4 v = pack_rec(Ts[bl * 97 + k0],     Ts[bl * 97 + k0 + 1],
                               Ts[bl * 97 + k0 + 8], Ts[bl * 97 + k0 + 9]);
            int tile = b >> 7;
            int nf   = (b >> 3) & 15;
            int gg   = b & 7;
            g_Trec[(size_t)tile * B_RECS + (nf * NS + s) * 32 + (gg * 4 + t2)] = v;
        }
    }
}

// ===========================================================================
// GEMM2 fused: H = tanh(A·T + b2); emits g_Arec records directly
// ===========================================================================
#define G_SMEM ((AG_RECS + B_RECS) * 16)   // 86016

__global__ void __launch_bounds__(256, 2)
gemm2_kernel(const float* __restrict__ b2, int B) {
    extern __shared__ char sm[];
    uint4* Af = (uint4*)sm;
    uint4* Bf = (uint4*)sm + AG_RECS;
    float* Hs = (float*)sm;                 // reused: [128 b][97]
    const int tid = threadIdx.x;
    const int wid = tid >> 5, lane = tid & 31;
    const int b0 = blockIdx.x * 128;

    {
        const u32 af = smem_u32(Af), bf = smem_u32(Bf);
        const uint4* Bsrc = g_Trec + (size_t)blockIdx.x * B_RECS;
        #pragma unroll
        for (int r = 0; r < AG_RECS / 256; r++)
            cp16(af + (r * 256 + tid) * 16, g_AGrec + r * 256 + tid);
        #pragma unroll
        for (int r = 0; r < B_RECS / 256; r++)
            cp16(bf + (r * 256 + tid) * 16, Bsrc + r * 256 + tid);
        asm volatile("cp.async.commit_group;");
        asm volatile("cp.async.wait_group 0;" ::: "memory");
    }
    __syncthreads();

    const int mf0 = (wid & 1) * 3;
    const int nf0 = (wid >> 1) * 4;

    float acc[3][4][4];
    #pragma unroll
    for (int i = 0; i < 3; i++)
        #pragma unroll
        for (int j = 0; j < 4; j++)
            #pragma unroll
            for (int c = 0; c < 4; c++) acc[i][j][c] = 0.0f;

    #pragma unroll
    for (int s = 0; s < NS; s++) {
        uint4 ar0[3], ar1[3];
        #pragma unroll
        for (int i = 0; i < 3; i++) {
            int mf = mf0 + i;
            ar0[i] = Af[((mf * NS + s) * 2 + 0) * 32 + lane];
            ar1[i] = Af[((mf * NS + s) * 2 + 1) * 32 + lane];
        }
        #pragma unroll
        for (int j = 0; j < 4; j++) {
            uint4 br = Bf[((nf0 + j) * NS + s) * 32 + lane];
            #pragma unroll
            for (int i = 0; i < 3; i++) {
                mma_bf16(acc[i][j][0], acc[i][j][1], acc[i][j][2], acc[i][j][3],
                         ar0[i].x, ar1[i].x, ar0[i].y, ar1[i].y, br.x, br.y);
                mma_bf16(acc[i][j][0], acc[i][j][1], acc[i][j][2], acc[i][j][3],
                         ar0[i].x, ar1[i].x, ar0[i].y, ar1[i].y, br.z, br.w);
                mma_bf16(acc[i][j][0], acc[i][j][1], acc[i][j][2], acc[i][j][3],
                         ar0[i].z, ar1[i].z, ar0[i].w, ar1[i].w, br.x, br.y);
            }
        }
    }

    __syncthreads();   // staging smem dead -> reuse as Hs

    const float b2v = b2[0];
    const int g = lane >> 2, t = lane & 3;
    #pragma unroll
    for (int j = 0; j < 4; j++) {
        int bcol = (nf0 + j) * 8 + 2 * t;
        #pragma unroll
        for (int i = 0; i < 3; i++) {
            int row = (mf0 + i) * 16 + g;
            Hs[bcol * 97 + row]           = tanhf(acc[i][j][0] + b2v);
            Hs[(bcol + 1) * 97 + row]     = tanhf(acc[i][j][1] + b2v);
            Hs[bcol * 97 + row + 8]       = tanhf(acc[i][j][2] + b2v);
            Hs[(bcol + 1) * 97 + row + 8] = tanhf(acc[i][j][3] + b2v);
        }
    }
    __syncthreads();

    for (int r = tid; r < A_RECS; r += 256) {
        int lane2 = r & 31;
        int rc    = (r >> 5) & 1;
        int rest  = r >> 6;
        int s     = rest % NS;
        int mf    = rest / NS;
        int ml = mf * 16 + rc * 8 + (lane2 >> 2);
        int k0 = s * 16 + 2 * (lane2 & 3);
        uint4 v = make_uint4(0, 0, 0, 0);
        if (b0 + ml < B) {
            const float* p = Hs + ml * 97 + k0;
            v = pack_rec(p[0], p[1], p[8], p[9]);
        }
        g_Arec[blockIdx.x * A_RECS + r] = v;
    }
}

// ===========================================================================
// FC GEMM — R14 form (proven fastest): per-tile blocks, 2/SM,
// cp.async staging, permuted STG.128 epilogue
// ===========================================================================
#define FC_SMEM ((A_RECS + B_RECS) * 16)  // 98304

__global__ void __launch_bounds__(256, 2)
fc_mma_kernel(const float* __restrict__ bfc, float* __restrict__ out, int B) {
    extern __shared__ char sm[];
    uint4* Af = (uint4*)sm;
    uint4* Bf = (uint4*)sm + A_RECS;

    const int tid  = threadIdx.x;
    const int wid  = tid >> 5;
    const int lane = tid & 31;
    const int m0   = blockIdx.y * 128;
    const int n0   = blockIdx.x * 128;

    {
        const u32 af = smem_u32(Af);
        const u32 bf = smem_u32(Bf);
        const uint4* Asrc = g_Arec + (size_t)blockIdx.y * A_RECS;
        const uint4* Bsrc = g_Brec + (size_t)blockIdx.x * B_RECS;
        #pragma unroll
        for (int r = 0; r < A_RECS / 256; r++)
            cp16(af + (r * 256 + tid) * 16, Asrc + r * 256 + tid);
        #pragma unroll
        for (int r = 0; r < B_RECS / 256; r++)
            cp16(bf + (r * 256 + tid) * 16, Bsrc + r * 256 + tid);
        asm volatile("cp.async.commit_group;");
        asm volatile("cp.async.wait_group 0;" ::: "memory");
    }
    __syncthreads();

    const int wm = wid & 3;
    const int wn = wid >> 2;
    const int mf0 = wm * 2;
    const int nf0 = wn * 8;

    float acc[2][8][4];
    #pragma unroll
    for (int i = 0; i < 2; i++)
        #pragma unroll
        for (int j = 0; j < 8; j++)
            #pragma unroll
            for (int c = 0; c < 4; c++) acc[i][j][c] = 0.0f;

    #pragma unroll
    for (int s = 0; s < NS; s++) {
        uint4 ar0[2], ar1[2];
        #pragma unroll
        for (int i = 0; i < 2; i++) {
            int mf = mf0 + i;
            ar0[i] = Af[((mf * NS + s) * 2 + 0) * 32 + lane];
            ar1[i] = Af[((mf * NS + s) * 2 + 1) * 32 + lane];
        }
        #pragma unroll
        for (int j = 0; j < 8; j++) {
            uint4 br = Bf[((nf0 + j) * NS + s) * 32 + lane];
            #pragma unroll
            for (int i = 0; i < 2; i++) {
                mma_bf16(acc[i][j][0], acc[i][j][1], acc[i][j][2], acc[i][j][3],
                         ar0[i].x, ar1[i].x, ar0[i].y, ar1[i].y, br.x, br.y);
                mma_bf16(acc[i][j][0], acc[i][j][1], acc[i][j][2], acc[i][j][3],
                         ar0[i].x, ar1[i].x, ar0[i].y, ar1[i].y, br.z, br.w);
                mma_bf16(acc[i][j][0], acc[i][j][1], acc[i][j][2], acc[i][j][3],
                         ar0[i].z, ar1[i].z, ar0[i].w, ar1[i].w, br.x, br.y);
            }
        }
    }

    // ---- Epilogue: permuted layout -> float4 stores ----
    const int g = lane >> 2, t = lane & 3;
    #pragma unroll
    for (int u = 0; u < 4; u++) {
        const int j0 = 2 * u, j1 = 2 * u + 1;
        const int nbase = n0 + 64 * wn + 16 * u + 4 * t;
        float4 bz = *(const float4*)(bfc + nbase);
        #pragma unroll
        for (int i = 0; i < 2; i++) {
            int mr0 = m0 + (mf0 + i) * 16 + g;
            if (mr0 < B) {
                float4 v = make_float4(acc[i][j0][0] + bz.x, acc[i][j0][1] + bz.y,
                                       acc[i][j1][0] + bz.z, acc[i][j1][1] + bz.w);
                *(float4*)(out + (size_t)mr0 * NOUT + nbase) = v;
            }
            int mr1 = mr0 + 8;
            if (mr1 < B) {
                float4 v = make_float4(acc[i][j0][2] + bz.x, acc[i][j0][3] + bz.y,
                                       acc[i][j1][2] + bz.z, acc[i][j1][3] + bz.w);
                *(float4*)(out + (size_t)mr1 * NOUT + nbase) = v;
            }
        }
    }
}

// ===========================================================================
// Launch
// ===========================================================================
extern "C" void kernel_launch(void* const* d_in, const int* in_sizes, int n_in,
                              void* d_out, int out_size) {
    const float* feature = (const float*)d_in[0];
    const int*   ei      = (const int*)  d_in[1];
    const float* ew      = (const float*)d_in[2];
    const float* W1      = (const float*)d_in[3];
    const float* b1      = (const float*)d_in[4];
    const float* W2      = (const float*)d_in[5];
    const float* b2      = (const float*)d_in[6];
    const float* Wfc     = (const float*)d_in[7];
    const float* bfc     = (const float*)d_in[8];
    float*       out     = (float*)d_out;

    const int B = in_sizes[0] / (NNODE * 3);
    const int E = in_sizes[1] / 2;
    const int nmt  = (B + 127) / 128;
    const int nt21 = (B + 20) / 21;

    cudaFuncSetAttribute(gemm1_kernel, cudaFuncAttributeMaxDynamicSharedMemorySize, G1_SMEM);
    cudaFuncSetAttribute(gemm2_kernel, cudaFuncAttributeMaxDynamicSharedMemorySize, G_SMEM);
    cudaFuncSetAttribute(fc_mma_kernel,cudaFuncAttributeMaxDynamicSharedMemorySize, FC_SMEM);

    build_graph_kernel<<<1, 256>>>(ei, ew, E);
    repack_ag_kernel<<<(AG_RECS + 255) / 256, 256>>>();

    { dim3 gb(B_RECS / 256, NNT); repack_b_kernel<<<gb, 256>>>(Wfc); }

    gemm1_kernel<<<nt21, 256, G1_SMEM>>>(feature, W1, b1, W2, B);
    gemm2_kernel<<<nmt, 256, G_SMEM>>>(b2, B);

    dim3 grid(NNT, nmt);
    fc_mma_kernel<<<grid, 256, FC_SMEM>>>(bfc, out, B);
}